// round 2
// baseline (speedup 1.0000x reference)
#include <cuda_runtime.h>

// Problem constants
#define B 256
#define T 512
#define H 512
#define O 2

// d_out layout (floats), reference return order: out, hidden, net_units, read_out_units
#define HID_OFF (B * O)                 // 512
#define NET_OFF (HID_OFF + B * H)       // 131584
#define RO_OFF  (NET_OFF + B * T * H)   // 67240448

#define KC  32   // K-chunk
#define PAD 34   // smem row pad (even -> 8B-aligned float2 reads, few conflicts)

// One recurrence step: net[:, t, :] = relu(x_proj_t + net[:, t-1, :] @ W_hh^T + b_hh + sigma*noise_t)
// Grid: (H/32, B/32) = (16, 8) = 128 CTAs, 256 threads.
// Thread (tm = tid>>3 in 0..31, tn = tid&7 in 0..7) computes row b0+tm, cols j0+4*tn..+3.
__global__ __launch_bounds__(256) void rnn_step_kernel(
    const float* __restrict__ input,   // [B,T,2]
    const float* __restrict__ sigma,   // [1]
    const float* __restrict__ noise,   // [B,T,H]
    const float* __restrict__ W_in,    // [H,2]
    const float* __restrict__ b_in,    // [H]
    const float* __restrict__ W_hh,    // [H,H]
    const float* __restrict__ b_hh,    // [H]
    float*       __restrict__ net,     // [B,T,H]  (= d_out + NET_OFF)
    int t)
{
    __shared__ float Hs[KC][PAD];   // Hs[k][m] = h_prev[b0+m][k0+k]
    __shared__ float Ws[KC][PAD];   // Ws[k][n] = W_hh[j0+n][k0+k]

    const int j0  = blockIdx.x * 32;
    const int b0  = blockIdx.y * 32;
    const int tid = threadIdx.x;
    const int tn  = tid & 7;    // 0..7  -> 4 output cols
    const int tm  = tid >> 3;   // 0..31 -> output row

    float acc0 = 0.f, acc1 = 0.f, acc2 = 0.f, acc3 = 0.f;

    if (t > 0) {
        // loader mapping: each thread fetches one float4 per tile per chunk
        const int lrow = tid >> 3;        // 0..31
        const int lk   = (tid & 7) * 4;   // 0,4,...,28

        const size_t hbase = ((size_t)b0 * T + (size_t)(t - 1)) * H;   // + m*T*H + k
        for (int k0 = 0; k0 < H; k0 += KC) {
            float4 hv = *(const float4*)(net  + hbase + (size_t)lrow * T * H + k0 + lk);
            float4 wv = *(const float4*)(W_hh + (size_t)(j0 + lrow) * H + k0 + lk);
            __syncthreads();   // previous chunk fully consumed
            Hs[lk + 0][lrow] = hv.x; Hs[lk + 1][lrow] = hv.y;
            Hs[lk + 2][lrow] = hv.z; Hs[lk + 3][lrow] = hv.w;
            Ws[lk + 0][lrow] = wv.x; Ws[lk + 1][lrow] = wv.y;
            Ws[lk + 2][lrow] = wv.z; Ws[lk + 3][lrow] = wv.w;
            __syncthreads();
            #pragma unroll
            for (int k = 0; k < KC; k++) {
                float  h   = Hs[k][tm];
                float2 w01 = *(const float2*)&Ws[k][tn * 4 + 0];
                float2 w23 = *(const float2*)&Ws[k][tn * 4 + 2];
                acc0 += h * w01.x;
                acc1 += h * w01.y;
                acc2 += h * w23.x;
                acc3 += h * w23.y;
            }
        }
    }

    // Epilogue: + x_proj + b_hh + sigma*noise, ReLU, store to net[:, t, :]
    const int b = b0 + tm;
    const int j = j0 + tn * 4;
    const float in0 = input[((size_t)b * T + t) * 2 + 0];
    const float in1 = input[((size_t)b * T + t) * 2 + 1];
    const float sn  = sigma[0];
    const float* nrow   = noise + ((size_t)b * T + t) * H + j;
    float*       outrow = net   + ((size_t)b * T + t) * H + j;

    float accs[4] = {acc0, acc1, acc2, acc3};
    float4 res;
    float* resp = &res.x;
    #pragma unroll
    for (int i = 0; i < 4; i++) {
        int   jj = j + i;
        float xp = in0 * W_in[jj * 2 + 0] + in1 * W_in[jj * 2 + 1] + b_in[jj];
        float v  = accs[i] + xp + b_hh[jj] + sn * nrow[i];
        resp[i]  = v > 0.f ? v : 0.f;
    }
    *(float4*)outrow = res;
}

// Readout: ro[b,t,o] = net[b,t,:] . W_fc[o,:] + b_fc[o]; also out = ro[:, T-1, :], hidden = net[:, T-1, :]
// One warp per (b,t) pair. Grid: B*T/8 CTAs of 256 threads (8 warps).
__global__ __launch_bounds__(256) void readout_kernel(
    const float* __restrict__ net,     // [B,T,H]
    const float* __restrict__ W_fc,    // [O,H]
    const float* __restrict__ b_fc,    // [O]
    float*       __restrict__ ro,      // [B,T,O]
    float*       __restrict__ out,     // [B,O]
    float*       __restrict__ hidden)  // [B,H]
{
    __shared__ float4 w0s[H / 4];
    __shared__ float4 w1s[H / 4];
    const int tid = threadIdx.x;
    if (tid < H / 4)            w0s[tid]          = ((const float4*)W_fc)[tid];
    else if (tid < 2 * (H / 4)) w1s[tid - H / 4]  = ((const float4*)(W_fc + H))[tid - H / 4];
    __syncthreads();

    const int warp = tid >> 5, lane = tid & 31;
    const int bt = blockIdx.x * 8 + warp;          // 0 .. B*T-1
    const int b = bt / T, t = bt % T;

    const float4* row = (const float4*)(net + (size_t)bt * H);
    float a0 = 0.f, a1 = 0.f;
    float4 vals[4];
    #pragma unroll
    for (int i = 0; i < 4; i++) {
        float4 v  = row[lane + 32 * i];
        float4 w0 = w0s[lane + 32 * i];
        float4 w1 = w1s[lane + 32 * i];
        vals[i] = v;
        a0 += v.x * w0.x + v.y * w0.y + v.z * w0.z + v.w * w0.w;
        a1 += v.x * w1.x + v.y * w1.y + v.z * w1.z + v.w * w1.w;
    }
    #pragma unroll
    for (int s = 16; s > 0; s >>= 1) {
        a0 += __shfl_xor_sync(0xFFFFFFFFu, a0, s);
        a1 += __shfl_xor_sync(0xFFFFFFFFu, a1, s);
    }
    if (lane == 0) {
        ro[(size_t)bt * 2 + 0] = a0 + b_fc[0];
        ro[(size_t)bt * 2 + 1] = a1 + b_fc[1];
    }
    if (t == T - 1) {
        if (lane == 0) {
            out[b * 2 + 0] = a0 + b_fc[0];
            out[b * 2 + 1] = a1 + b_fc[1];
        }
        float4* hid = (float4*)(hidden + (size_t)b * H);
        #pragma unroll
        for (int i = 0; i < 4; i++) hid[lane + 32 * i] = vals[i];
    }
}

extern "C" void kernel_launch(void* const* d_in, const int* in_sizes, int n_in,
                              void* d_out, int out_size)
{
    const float* input = (const float*)d_in[0];
    const float* sigma = (const float*)d_in[1];
    const float* noise = (const float*)d_in[2];
    const float* W_in  = (const float*)d_in[3];
    const float* b_in  = (const float*)d_in[4];
    const float* W_hh  = (const float*)d_in[5];
    const float* b_hh  = (const float*)d_in[6];
    const float* W_fc  = (const float*)d_in[7];
    const float* b_fc  = (const float*)d_in[8];

    float* out    = (float*)d_out;
    float* hidden = out + HID_OFF;
    float* net    = out + NET_OFF;
    float* ro     = out + RO_OFF;

    dim3 grid(H / 32, B / 32);   // 16 x 8 = 128 CTAs
    for (int t = 0; t < T; t++) {
        rnn_step_kernel<<<grid, 256>>>(input, sigma, noise, W_in, b_in, W_hh, b_hh, net, t);
    }
    readout_kernel<<<(B * T) / 8, 256>>>(net, W_fc, b_fc, ro, out, hidden);
}